// round 4
// baseline (speedup 1.0000x reference)
#include <cuda_runtime.h>
#include <cuda_bf16.h>

// One fused kernel, no memcpy nodes. E (extrinsic 4x4) and K (intrinsic 3x4)
// are staged per-block into shared memory, then broadcast-read.
// Each thread processes 4 consecutive points with pure 128-bit gmem traffic.

__device__ __forceinline__ void project_one(
    float px, float py, float pz,
    float4 q,
    float sx, float sy, float sz,
    const float* __restrict__ E, const float* __restrict__ K,
    float& ppx, float& ppy, float& zout,
    float4& cov)
{
    // ---- camera transform: cam = E @ [p;1] ----
    const float camx = fmaf(E[0], px, fmaf(E[1], py, fmaf(E[2], pz, E[3])));
    const float camy = fmaf(E[4], px, fmaf(E[5], py, fmaf(E[6], pz, E[7])));
    const float camz = fmaf(E[8], px, fmaf(E[9], py, fmaf(E[10], pz, E[11])));
    const float camw = fmaf(E[12], px, fmaf(E[13], py, fmaf(E[14], pz, E[15])));

    const float invw = __frcp_rn(camw);
    const float c3x = camx * invw;
    const float c3y = camy * invw;
    const float c3z = camz * invw;

    // ---- projection: proj = K @ [cam3;1]; pp = proj[:2]/proj[2] ----
    const float fx = K[0], fy = K[5];
    const float projx = fmaf(fx, c3x, fmaf(K[1], c3y, fmaf(K[2], c3z, K[3])));
    const float projy = fmaf(K[4], c3x, fmaf(fy, c3y, fmaf(K[6], c3z, K[7])));
    const float projz = fmaf(K[8], c3x, fmaf(K[9], c3y, fmaf(K[10], c3z, K[11])));
    const float invpz = __frcp_rn(projz);
    ppx = projx * invpz;
    ppy = projy * invpz;
    zout = camz;

    // ---- quaternion -> rotation ----
    const float qn = rsqrtf(fmaf(q.x, q.x, fmaf(q.y, q.y, fmaf(q.z, q.z, q.w * q.w))));
    const float w = q.x * qn, x = q.y * qn, y = q.z * qn, z = q.w * qn;

    const float r00 = 1.0f - 2.0f * (y * y + z * z);
    const float r01 = 2.0f * (x * y - w * z);
    const float r02 = 2.0f * (x * z + w * y);
    const float r10 = 2.0f * (x * y + w * z);
    const float r11 = 1.0f - 2.0f * (x * x + z * z);
    const float r12 = 2.0f * (y * z - w * x);
    const float r20 = 2.0f * (x * z - w * y);
    const float r21 = 2.0f * (y * z + w * x);
    const float r22 = 1.0f - 2.0f * (x * x + y * y);

    // ---- M = R * diag(s); cov3d = M M^T (symmetric) ----
    const float m00 = r00 * sx, m01 = r01 * sy, m02 = r02 * sz;
    const float m10 = r10 * sx, m11 = r11 * sy, m12 = r12 * sz;
    const float m20 = r20 * sx, m21 = r21 * sy, m22 = r22 * sz;

    const float s00 = fmaf(m00, m00, fmaf(m01, m01, m02 * m02));
    const float s01 = fmaf(m00, m10, fmaf(m01, m11, m02 * m12));
    const float s02 = fmaf(m00, m20, fmaf(m01, m21, m02 * m22));
    const float s11 = fmaf(m10, m10, fmaf(m11, m11, m12 * m12));
    const float s12 = fmaf(m10, m20, fmaf(m11, m21, m12 * m22));
    const float s22 = fmaf(m20, m20, fmaf(m21, m21, m22 * m22));

    // ---- T2 = J[:2] @ E[:3,:3] ----
    const float invz = __frcp_rn(c3z);
    const float invz2 = invz * invz;
    const float a = fx * invz;
    const float b = fy * invz;
    const float cterm = -fx * c3x * invz2;
    const float dterm = -fy * c3y * invz2;

    const float t00 = fmaf(a, E[0], cterm * E[8]);
    const float t01 = fmaf(a, E[1], cterm * E[9]);
    const float t02 = fmaf(a, E[2], cterm * E[10]);
    const float t10 = fmaf(b, E[4], dterm * E[8]);
    const float t11 = fmaf(b, E[5], dterm * E[9]);
    const float t12 = fmaf(b, E[6], dterm * E[10]);

    // ---- cov2d = T2 @ cov3d @ T2^T ----
    const float u0x = fmaf(s00, t00, fmaf(s01, t01, s02 * t02));
    const float u0y = fmaf(s01, t00, fmaf(s11, t01, s12 * t02));
    const float u0z = fmaf(s02, t00, fmaf(s12, t01, s22 * t02));
    const float u1x = fmaf(s00, t10, fmaf(s01, t11, s02 * t12));
    const float u1y = fmaf(s01, t10, fmaf(s11, t11, s12 * t12));
    const float u1z = fmaf(s02, t10, fmaf(s12, t11, s22 * t12));

    cov.x = fmaf(t00, u0x, fmaf(t01, u0y, t02 * u0z));
    cov.y = fmaf(t00, u1x, fmaf(t01, u1y, t02 * u1z));
    cov.z = fmaf(t10, u0x, fmaf(t11, u0y, t12 * u0z));
    cov.w = fmaf(t10, u1x, fmaf(t11, u1y, t12 * u1z));
}

__global__ __launch_bounds__(256)
void gaussian_project4_kernel(const float4* __restrict__ points4,  // 3N/4 float4
                              const float4* __restrict__ quats4,   // N float4
                              const float4* __restrict__ scales4,  // 3N/4 float4
                              const float* __restrict__ extr,      // 16 floats
                              const float* __restrict__ intr,      // 12 floats
                              float* __restrict__ out,             // 7N floats
                              int N4) {                             // N/4
    __shared__ float sE[16];
    __shared__ float sK[12];
    {
        int lt = threadIdx.x;
        if (lt < 16) sE[lt] = extr[lt];
        else if (lt < 28) sK[lt - 16] = intr[lt - 16];
    }
    __syncthreads();

    const int t = blockIdx.x * blockDim.x + threadIdx.x;
    if (t >= N4) return;

    // ---- front-batched 128-bit loads (high MLP) ----
    const float4 pA = points4[3 * t + 0];
    const float4 pB = points4[3 * t + 1];
    const float4 pC = points4[3 * t + 2];
    const float4 q0 = quats4[4 * t + 0];
    const float4 q1 = quats4[4 * t + 1];
    const float4 q2 = quats4[4 * t + 2];
    const float4 q3 = quats4[4 * t + 3];
    const float4 sA = scales4[3 * t + 0];
    const float4 sB = scales4[3 * t + 1];
    const float4 sC = scales4[3 * t + 2];

    float ppx0, ppy0, z0; float4 c0;
    float ppx1, ppy1, z1; float4 c1;
    float ppx2, ppy2, z2; float4 c2;
    float ppx3, ppy3, z3; float4 c3;

    project_one(pA.x, pA.y, pA.z, q0, sA.x, sA.y, sA.z, sE, sK, ppx0, ppy0, z0, c0);
    project_one(pA.w, pB.x, pB.y, q1, sA.w, sB.x, sB.y, sE, sK, ppx1, ppy1, z1, c1);
    project_one(pB.z, pB.w, pC.x, q2, sB.z, sB.w, sC.x, sE, sK, ppx2, ppy2, z2, c2);
    project_one(pC.y, pC.z, pC.w, q3, sC.y, sC.z, sC.w, sE, sK, ppx3, ppy3, z3, c3);

    const int N = N4 * 4;

    // pp: [2N] floats -> 2 float4 per thread
    float4* out_pp = reinterpret_cast<float4*>(out);
    out_pp[2 * t + 0] = make_float4(ppx0, ppy0, ppx1, ppy1);
    out_pp[2 * t + 1] = make_float4(ppx2, ppy2, ppx3, ppy3);

    // z: [N] floats at offset 2N (divisible by 4) -> 1 float4
    float4* out_z = reinterpret_cast<float4*>(out + 2 * (size_t)N);
    out_z[t] = make_float4(z0, z1, z2, z3);

    // cov: [4N] floats at offset 3N (divisible by 4) -> 4 float4
    float4* out_cov = reinterpret_cast<float4*>(out + 3 * (size_t)N);
    out_cov[4 * t + 0] = c0;
    out_cov[4 * t + 1] = c1;
    out_cov[4 * t + 2] = c2;
    out_cov[4 * t + 3] = c3;
}

extern "C" void kernel_launch(void* const* d_in, const int* in_sizes, int n_in,
                              void* d_out, int out_size) {
    const float4* points4 = (const float4*)d_in[0];
    const float4* quats4  = (const float4*)d_in[1];
    const float4* scales4 = (const float4*)d_in[2];
    const float* extr = (const float*)d_in[3];   // 16 floats
    const float* intr = (const float*)d_in[4];   // 12 floats

    const int N = in_sizes[0] / 3;
    const int N4 = N / 4;   // N = 2,000,000 -> divisible by 4

    const int threads = 256;
    const int blocks = (N4 + threads - 1) / threads;
    gaussian_project4_kernel<<<blocks, threads>>>(points4, quats4, scales4,
                                                  extr, intr,
                                                  (float*)d_out, N4);
}

// round 5
// speedup vs baseline: 1.0106x; 1.0106x over previous
#include <cuda_runtime.h>
#include <cuda_bf16.h>

// Single-kernel graph (no memcpy nodes). E (extrinsic 4x4, 16 floats) and
// K (intrinsic 3x4, 12 floats) staged per-block into shared memory.
// Scalar per-point processing: 32-reg profile, high occupancy (R3 layout).

__global__ __launch_bounds__(256)
void gaussian_project_kernel(const float* __restrict__ points,     // [N,3]
                             const float4* __restrict__ quats,     // [N,4]
                             const float* __restrict__ scales,     // [N,3]
                             const float* __restrict__ extr,       // 16 floats
                             const float* __restrict__ intr,       // 12 floats
                             float* __restrict__ out,              // [7N]
                             int N) {
    __shared__ float E[16];
    __shared__ float K[12];
    {
        const int lt = threadIdx.x;
        if (lt < 16) E[lt] = extr[lt];
        else if (lt < 28) K[lt - 16] = intr[lt - 16];
    }
    __syncthreads();

    const int i = blockIdx.x * blockDim.x + threadIdx.x;
    if (i >= N) return;

    // ---- loads ----
    const float px = points[3 * i + 0];
    const float py = points[3 * i + 1];
    const float pz = points[3 * i + 2];
    const float4 q = quats[i];
    const float sx = scales[3 * i + 0];
    const float sy = scales[3 * i + 1];
    const float sz = scales[3 * i + 2];

    // ---- camera transform: cam = E @ [p;1] ----
    const float camx = fmaf(E[0], px, fmaf(E[1], py, fmaf(E[2], pz, E[3])));
    const float camy = fmaf(E[4], px, fmaf(E[5], py, fmaf(E[6], pz, E[7])));
    const float camz = fmaf(E[8], px, fmaf(E[9], py, fmaf(E[10], pz, E[11])));
    const float camw = fmaf(E[12], px, fmaf(E[13], py, fmaf(E[14], pz, E[15])));

    const float invw = __frcp_rn(camw);
    const float c3x = camx * invw;
    const float c3y = camy * invw;
    const float c3z = camz * invw;

    // ---- projection: proj = K @ [cam3;1]; pp = proj[:2]/proj[2] ----
    const float fx = K[0], fy = K[5];
    const float projx = fmaf(fx, c3x, fmaf(K[1], c3y, fmaf(K[2], c3z, K[3])));
    const float projy = fmaf(K[4], c3x, fmaf(fy, c3y, fmaf(K[6], c3z, K[7])));
    const float projz = fmaf(K[8], c3x, fmaf(K[9], c3y, fmaf(K[10], c3z, K[11])));
    const float invpz = __frcp_rn(projz);
    const float ppx = projx * invpz;
    const float ppy = projy * invpz;

    // ---- quaternion -> rotation ----
    const float qn = rsqrtf(fmaf(q.x, q.x, fmaf(q.y, q.y, fmaf(q.z, q.z, q.w * q.w))));
    const float w = q.x * qn, x = q.y * qn, y = q.z * qn, z = q.w * qn;

    const float r00 = 1.0f - 2.0f * (y * y + z * z);
    const float r01 = 2.0f * (x * y - w * z);
    const float r02 = 2.0f * (x * z + w * y);
    const float r10 = 2.0f * (x * y + w * z);
    const float r11 = 1.0f - 2.0f * (x * x + z * z);
    const float r12 = 2.0f * (y * z - w * x);
    const float r20 = 2.0f * (x * z - w * y);
    const float r21 = 2.0f * (y * z + w * x);
    const float r22 = 1.0f - 2.0f * (x * x + y * y);

    // ---- M = R * diag(s); cov3d = M M^T (symmetric) ----
    const float m00 = r00 * sx, m01 = r01 * sy, m02 = r02 * sz;
    const float m10 = r10 * sx, m11 = r11 * sy, m12 = r12 * sz;
    const float m20 = r20 * sx, m21 = r21 * sy, m22 = r22 * sz;

    const float s00 = fmaf(m00, m00, fmaf(m01, m01, m02 * m02));
    const float s01 = fmaf(m00, m10, fmaf(m01, m11, m02 * m12));
    const float s02 = fmaf(m00, m20, fmaf(m01, m21, m02 * m22));
    const float s11 = fmaf(m10, m10, fmaf(m11, m11, m12 * m12));
    const float s12 = fmaf(m10, m20, fmaf(m11, m21, m12 * m22));
    const float s22 = fmaf(m20, m20, fmaf(m21, m21, m22 * m22));

    // ---- T2 = J[:2] @ E[:3,:3] ----
    const float invz = __frcp_rn(c3z);
    const float invz2 = invz * invz;
    const float a = fx * invz;
    const float b = fy * invz;
    const float cterm = -fx * c3x * invz2;
    const float dterm = -fy * c3y * invz2;

    const float t00 = fmaf(a, E[0], cterm * E[8]);
    const float t01 = fmaf(a, E[1], cterm * E[9]);
    const float t02 = fmaf(a, E[2], cterm * E[10]);
    const float t10 = fmaf(b, E[4], dterm * E[8]);
    const float t11 = fmaf(b, E[5], dterm * E[9]);
    const float t12 = fmaf(b, E[6], dterm * E[10]);

    // ---- cov2d = T2 @ cov3d @ T2^T ----
    const float u0x = fmaf(s00, t00, fmaf(s01, t01, s02 * t02));
    const float u0y = fmaf(s01, t00, fmaf(s11, t01, s12 * t02));
    const float u0z = fmaf(s02, t00, fmaf(s12, t01, s22 * t02));
    const float u1x = fmaf(s00, t10, fmaf(s01, t11, s02 * t12));
    const float u1y = fmaf(s01, t10, fmaf(s11, t11, s12 * t12));
    const float u1z = fmaf(s02, t10, fmaf(s12, t11, s22 * t12));

    const float c00 = fmaf(t00, u0x, fmaf(t01, u0y, t02 * u0z));
    const float c01 = fmaf(t00, u1x, fmaf(t01, u1y, t02 * u1z));
    const float c10 = fmaf(t10, u0x, fmaf(t11, u0y, t12 * u0z));
    const float c11 = fmaf(t10, u1x, fmaf(t11, u1y, t12 * u1z));

    // ---- stores: [2N pp][N z][4N cov] ----
    reinterpret_cast<float2*>(out)[i] = make_float2(ppx, ppy);
    out[2 * (size_t)N + i] = camz;
    reinterpret_cast<float4*>(out + 3 * (size_t)N)[i] = make_float4(c00, c01, c10, c11);
}

extern "C" void kernel_launch(void* const* d_in, const int* in_sizes, int n_in,
                              void* d_out, int out_size) {
    const float* points = (const float*)d_in[0];
    const float4* quats = (const float4*)d_in[1];
    const float* scales = (const float*)d_in[2];
    const float* extr = (const float*)d_in[3];   // 16 floats
    const float* intr = (const float*)d_in[4];   // 12 floats

    const int N = in_sizes[0] / 3;

    const int threads = 256;
    const int blocks = (N + threads - 1) / threads;
    gaussian_project_kernel<<<blocks, threads>>>(points, quats, scales,
                                                 extr, intr,
                                                 (float*)d_out, N);
}